// round 3
// baseline (speedup 1.0000x reference)
#include <cuda_runtime.h>
#include <cuda_bf16.h>
#include <cstdint>

#define B_ 8
#define L_ 2048
#define V_ 10000
#define H_ 512

static const long long LH = (long long)L_ * H_;       // 1048576
static const long long LL = (long long)L_ * L_;       // 4194304

// ---------------- static device scratch (no allocations) ----------------
__device__ float g_embproj[V_ * H_];                   // 20.5 MB
__device__ float g_z[B_ * L_ * H_];                    // 33.5 MB
__device__ float g_P[(size_t)B_ * L_ * L_];            // 134 MB
__device__ float g_av[B_ * L_ * H_];                   // 33.5 MB
__device__ float g_dec[B_ * L_ * H_];                  // 33.5 MB

// ======================================================================
// fp32 NT GEMM: C[M,N] = A[M,K] * B[N,K]^T (+bias) (+=C)
// flags: bit0 = accumulate into C, bit1 = causal tile skip (skip bx > by)
// Batched over blockIdx.z with element strides sA/sB/sC.
// 128x128 tile, BK=16, 256 threads, 8x8 per thread. K % 16 == 0, N % 4 == 0.
// ======================================================================
__global__ __launch_bounds__(256) void gemm_nt(
    const float* __restrict__ A, int lda, long long sA,
    const float* __restrict__ B, int ldb, long long sB,
    float* __restrict__ C, int ldc, long long sC,
    int M, int N, int K,
    const float* __restrict__ bias, int flags)
{
    if ((flags & 2) && blockIdx.x > blockIdx.y) return;
    A += (long long)blockIdx.z * sA;
    B += (long long)blockIdx.z * sB;
    C += (long long)blockIdx.z * sC;

    __shared__ float As[16][128];
    __shared__ float Bs[16][128];

    const int tid = threadIdx.x;
    const int m0 = blockIdx.y * 128;
    const int n0 = blockIdx.x * 128;

    const int lr = tid >> 1;            // 0..127 row within tile (loader)
    const int lk = (tid & 1) << 3;      // 0 or 8  k offset (loader)
    const float* Ap = A + (long long)(m0 + lr) * lda + lk;
    const float* Bp = B + (long long)(n0 + lr) * ldb + lk;
    const bool aok = (m0 + lr) < M;
    const bool bok = (n0 + lr) < N;

    const int tr = (tid >> 4) << 3;     // C row offset for this thread
    const int tc = (tid & 15) << 3;     // C col offset for this thread

    float acc[8][8];
#pragma unroll
    for (int i = 0; i < 8; i++)
#pragma unroll
        for (int j = 0; j < 8; j++) acc[i][j] = 0.f;

    for (int k0 = 0; k0 < K; k0 += 16) {
        float4 a0 = make_float4(0.f,0.f,0.f,0.f), a1 = a0, b0 = a0, b1 = a0;
        if (aok) { a0 = *(const float4*)(Ap + k0); a1 = *(const float4*)(Ap + k0 + 4); }
        if (bok) { b0 = *(const float4*)(Bp + k0); b1 = *(const float4*)(Bp + k0 + 4); }

        As[lk+0][lr]=a0.x; As[lk+1][lr]=a0.y; As[lk+2][lr]=a0.z; As[lk+3][lr]=a0.w;
        As[lk+4][lr]=a1.x; As[lk+5][lr]=a1.y; As[lk+6][lr]=a1.z; As[lk+7][lr]=a1.w;
        Bs[lk+0][lr]=b0.x; Bs[lk+1][lr]=b0.y; Bs[lk+2][lr]=b0.z; Bs[lk+3][lr]=b0.w;
        Bs[lk+4][lr]=b1.x; Bs[lk+5][lr]=b1.y; Bs[lk+6][lr]=b1.z; Bs[lk+7][lr]=b1.w;
        __syncthreads();

#pragma unroll
        for (int kk = 0; kk < 16; kk++) {
            float4 x0 = *(const float4*)&As[kk][tr];
            float4 x1 = *(const float4*)&As[kk][tr + 4];
            float4 y0 = *(const float4*)&Bs[kk][tc];
            float4 y1 = *(const float4*)&Bs[kk][tc + 4];
            float av_[8] = {x0.x,x0.y,x0.z,x0.w,x1.x,x1.y,x1.z,x1.w};
            float bv_[8] = {y0.x,y0.y,y0.z,y0.w,y1.x,y1.y,y1.z,y1.w};
#pragma unroll
            for (int i = 0; i < 8; i++)
#pragma unroll
                for (int j = 0; j < 8; j++)
                    acc[i][j] = fmaf(av_[i], bv_[j], acc[i][j]);
        }
        __syncthreads();
    }

#pragma unroll
    for (int i = 0; i < 8; i++) {
        const int r = m0 + tr + i;
        if (r >= M) continue;
        float* Crow = C + (long long)r * ldc;
#pragma unroll
        for (int jj = 0; jj < 2; jj++) {
            const int c = n0 + tc + jj * 4;
            if (c >= N) continue;   // all N here are multiples of 4
            float4 v;
            v.x = acc[i][jj*4+0]; v.y = acc[i][jj*4+1];
            v.z = acc[i][jj*4+2]; v.w = acc[i][jj*4+3];
            if (bias) { v.x += bias[c]; v.y += bias[c+1]; v.z += bias[c+2]; v.w += bias[c+3]; }
            if (flags & 1) {
                float4 o = *(const float4*)(Crow + c);
                v.x += o.x; v.y += o.y; v.z += o.z; v.w += o.w;
            }
            *(float4*)(Crow + c) = v;
        }
    }
}

// ======================================================================
// fp32 NN GEMM: C[M,N] = A[M,K] * B[K,N]
// klimit_flag: K effective per row tile = min(K, (blockIdx.y+1)*128)
// (causal P @ z). K multiple of 16, N multiple of 8.
// ======================================================================
__global__ __launch_bounds__(256) void gemm_nn(
    const float* __restrict__ A, int lda, long long sA,
    const float* __restrict__ B, int ldb, long long sB,
    float* __restrict__ C, int ldc, long long sC,
    int M, int N, int K, int klimit_flag)
{
    A += (long long)blockIdx.z * sA;
    B += (long long)blockIdx.z * sB;
    C += (long long)blockIdx.z * sC;

    __shared__ float As[16][128];
    __shared__ float Bs[16][128];

    const int tid = threadIdx.x;
    const int m0 = blockIdx.y * 128;
    const int n0 = blockIdx.x * 128;
    const int K_eff = klimit_flag ? min(K, ((int)blockIdx.y + 1) * 128) : K;

    const int lr = tid >> 1;
    const int lk = (tid & 1) << 3;
    const float* Ap = A + (long long)(m0 + lr) * lda + lk;
    const bool aok = (m0 + lr) < M;

    const int bkr = tid >> 4;            // 0..15 : k row (B loader)
    const int bnc = (tid & 15) << 3;     // 0..120: n col (B loader)
    const float* Bp = B + (long long)bkr * ldb + n0 + bnc;
    const bool bok = (n0 + bnc) < N;

    const int tr = (tid >> 4) << 3;
    const int tc = (tid & 15) << 3;

    float acc[8][8];
#pragma unroll
    for (int i = 0; i < 8; i++)
#pragma unroll
        for (int j = 0; j < 8; j++) acc[i][j] = 0.f;

    for (int k0 = 0; k0 < K_eff; k0 += 16) {
        float4 a0 = make_float4(0.f,0.f,0.f,0.f), a1 = a0, b0 = a0, b1 = a0;
        if (aok) { a0 = *(const float4*)(Ap + k0); a1 = *(const float4*)(Ap + k0 + 4); }
        if (bok) {
            b0 = *(const float4*)(Bp + (long long)k0 * ldb);
            b1 = *(const float4*)(Bp + (long long)k0 * ldb + 4);
        }
        As[lk+0][lr]=a0.x; As[lk+1][lr]=a0.y; As[lk+2][lr]=a0.z; As[lk+3][lr]=a0.w;
        As[lk+4][lr]=a1.x; As[lk+5][lr]=a1.y; As[lk+6][lr]=a1.z; As[lk+7][lr]=a1.w;
        *(float4*)&Bs[bkr][bnc]     = b0;
        *(float4*)&Bs[bkr][bnc + 4] = b1;
        __syncthreads();

#pragma unroll
        for (int kk = 0; kk < 16; kk++) {
            float4 x0 = *(const float4*)&As[kk][tr];
            float4 x1 = *(const float4*)&As[kk][tr + 4];
            float4 y0 = *(const float4*)&Bs[kk][tc];
            float4 y1 = *(const float4*)&Bs[kk][tc + 4];
            float av_[8] = {x0.x,x0.y,x0.z,x0.w,x1.x,x1.y,x1.z,x1.w};
            float bv_[8] = {y0.x,y0.y,y0.z,y0.w,y1.x,y1.y,y1.z,y1.w};
#pragma unroll
            for (int i = 0; i < 8; i++)
#pragma unroll
                for (int j = 0; j < 8; j++)
                    acc[i][j] = fmaf(av_[i], bv_[j], acc[i][j]);
        }
        __syncthreads();
    }

#pragma unroll
    for (int i = 0; i < 8; i++) {
        const int r = m0 + tr + i;
        if (r >= M) continue;
        float* Crow = C + (long long)r * ldc;
#pragma unroll
        for (int jj = 0; jj < 2; jj++) {
            const int c = n0 + tc + jj * 4;
            if (c >= N) continue;
            float4 v;
            v.x = acc[i][jj*4+0]; v.y = acc[i][jj*4+1];
            v.z = acc[i][jj*4+2]; v.w = acc[i][jj*4+3];
            *(float4*)(Crow + c) = v;
        }
    }
}

// ======================================================================
// RNN: one 8-CTA cluster per batch element. CTA rank owns rows
// [rank*64, rank*64+64) of W_hh in registers (64 floats/thread).
// Thread t: row = t&63, kgroup = t>>6 (k in [kg*64, kg*64+64)).
// Warp-uniform h addresses -> broadcast LDS.128. Double-buffered h,
// one cluster barrier per step.
// ======================================================================
__global__ void __cluster_dims__(8, 1, 1) __launch_bounds__(512, 1)
rnn_kernel(const int* __restrict__ batch,
           const float* __restrict__ embproj,
           const float* __restrict__ W_hh,
           const float* __restrict__ b_hh,
           float* __restrict__ z)
{
    __shared__ float hbuf[2][512];
    __shared__ float part[8][64];

    const int t    = threadIdx.x;
    const int rank = blockIdx.x & 7;
    const int b    = blockIdx.x >> 3;
    const int row  = t & 63;
    const int kg   = t >> 6;
    const int grow = rank * 64 + row;   // global output row this thread helps

    // Load W_hh slice into registers: w[i] = W_hh[grow][kg*64 + i]
    float w[64];
    {
        const float* wp = W_hh + (long long)grow * H_ + kg * 64;
#pragma unroll
        for (int j = 0; j < 16; j++) {
            float4 v = *(const float4*)(wp + 4 * j);
            w[4*j+0] = v.x; w[4*j+1] = v.y; w[4*j+2] = v.z; w[4*j+3] = v.w;
        }
    }

    float bh = 0.f, xt = 0.f;
    if (t < 64) bh = b_hh[rank * 64 + t];

    hbuf[0][t] = 0.f;                   // h0 = 0 (local copy, all 512 entries)

    if (t < 64) {                       // prefetch x_proj for step 0
        int tok = batch[b * L_ + 0];
        xt = embproj[(long long)tok * H_ + rank * 64 + t];
    }
    __syncthreads();

    int p = 0;
    for (int step = 0; step < L_; ++step) {
        // ---- partial dot products over this thread's k-group ----
        const float4* h4 = (const float4*)hbuf[p];
        float s = 0.f;
#pragma unroll
        for (int j = 0; j < 16; j++) {
            float4 hv = h4[kg * 16 + j];     // warp-uniform address: broadcast
            s = fmaf(w[4*j+0], hv.x, s);
            s = fmaf(w[4*j+1], hv.y, s);
            s = fmaf(w[4*j+2], hv.z, s);
            s = fmaf(w[4*j+3], hv.w, s);
        }
        part[kg][row] = s;

        // prefetch next step's x_proj while waiting
        float xtn = 0.f;
        if (t < 64 && step + 1 < L_) {
            int tk = batch[b * L_ + step + 1];
            xtn = embproj[(long long)tk * H_ + rank * 64 + t];
        }
        __syncthreads();

        if (t < 64) {
            float v = part[0][t] + part[1][t] + part[2][t] + part[3][t]
                    + part[4][t] + part[5][t] + part[6][t] + part[7][t];
            v = tanhf(xt + v + bh);
            z[((long long)(b * L_ + step)) * H_ + rank * 64 + t] = v;

            // distribute new h value to every CTA's other h buffer
            uint32_t la = (uint32_t)__cvta_generic_to_shared(&hbuf[p ^ 1][rank * 64 + t]);
#pragma unroll
            for (int r = 0; r < 8; r++) {
                uint32_t ra;
                asm volatile("mapa.shared::cluster.u32 %0, %1, %2;"
                             : "=r"(ra) : "r"(la), "r"(r));
                asm volatile("st.shared::cluster.f32 [%0], %1;"
                             :: "r"(ra), "f"(v) : "memory");
            }
        }
        asm volatile("barrier.cluster.arrive.aligned;" ::: "memory");
        asm volatile("barrier.cluster.wait.aligned;"   ::: "memory");
        xt = xtn;
        p ^= 1;
    }
}

// ======================================================================
// Row softmax over strict-causal scores (in place in g_P).
// exp(-1e9 - m) underflows to exactly 0 in fp32, so masked entries
// contribute nothing -- matching the reference. Zeros are written for
// j in [i, diagonal tile end) so the P@z GEMM (tile-limited) is exact.
// Row 0 (empty kept-set) is handled by av0_mean afterwards.
// ======================================================================
__global__ __launch_bounds__(256) void softmax_rows(float* __restrict__ P)
{
    const int i = blockIdx.x;
    const int b = blockIdx.y;
    float* row = P + (size_t)b * LL + (size_t)i * L_;
    const int len = i;                        // kept entries: j < i
    const int tileEnd = ((i >> 7) + 1) << 7;  // diagonal-tile boundary
    const int tid = threadIdx.x;

    __shared__ float sm[8];
    __shared__ float bc[2];

    if (len > 0) {
        // pass 1: max
        float m = -1e30f;
        for (int j = tid; j < len; j += 256) m = fmaxf(m, row[j]);
#pragma unroll
        for (int o = 16; o; o >>= 1) m = fmaxf(m, __shfl_xor_sync(~0u, m, o));
        if ((tid & 31) == 0) sm[tid >> 5] = m;
        __syncthreads();
        if (tid == 0) {
            float v = sm[0];
            for (int wgt = 1; wgt < 8; wgt++) v = fmaxf(v, sm[wgt]);
            bc[0] = v;
        }
        __syncthreads();
        m = bc[0];

        // pass 2: sum of exp
        float s = 0.f;
        for (int j = tid; j < len; j += 256) s += expf(row[j] - m);
#pragma unroll
        for (int o = 16; o; o >>= 1) s += __shfl_xor_sync(~0u, s, o);
        if ((tid & 31) == 0) sm[tid >> 5] = s;
        __syncthreads();
        if (tid == 0) {
            float v = sm[0];
            for (int wgt = 1; wgt < 8; wgt++) v += sm[wgt];
            bc[1] = 1.f / v;
        }
        __syncthreads();
        const float inv = bc[1];

        // pass 3: write probabilities
        for (int j = tid; j < len; j += 256) row[j] = expf(row[j] - m) * inv;
    }
    // zero [len, tileEnd)
    for (int j = len + tid; j < tileEnd; j += 256) row[j] = 0.f;
}

// ======================================================================
// av[b][0][:] = mean over all 2048 rows of z[b]  (reference row-0 softmax
// of an all -1e9 row is uniform over ALL positions).
// One block per batch, 512 threads = 128 float4-columns x 4 j-groups.
// ======================================================================
__global__ __launch_bounds__(512) void av0_mean(const float* __restrict__ z,
                                                float* __restrict__ av)
{
    const int b = blockIdx.x;
    const float4* zb = (const float4*)(z + (size_t)b * LH);
    const int tid = threadIdx.x;
    const int hc = tid & 127;     // float4 column
    const int jg = tid >> 7;      // 0..3

    float4 acc = make_float4(0.f, 0.f, 0.f, 0.f);
#pragma unroll 8
    for (int j = jg * 512; j < (jg + 1) * 512; j++) {
        float4 v = zb[(long long)j * 128 + hc];
        acc.x += v.x; acc.y += v.y; acc.z += v.z; acc.w += v.w;
    }
    __shared__ float4 part[4][128];
    part[jg][hc] = acc;
    __syncthreads();
    if (tid < 128) {
        float4 s = part[0][tid];
        float4 p1 = part[1][tid], p2 = part[2][tid], p3 = part[3][tid];
        s.x = (s.x + p1.x + p2.x + p3.x) * (1.f / L_);
        s.y = (s.y + p1.y + p2.y + p3.y) * (1.f / L_);
        s.z = (s.z + p1.z + p2.z + p3.z) * (1.f / L_);
        s.w = (s.w + p1.w + p2.w + p3.w) * (1.f / L_);
        ((float4*)(av + (size_t)b * LH))[tid] = s;
    }
}

// ======================================================================
extern "C" void kernel_launch(void* const* d_in, const int* in_sizes, int n_in,
                              void* d_out, int out_size)
{
    const int*   batch = (const int*)  d_in[0];
    const float* emb   = (const float*)d_in[1];
    const float* W_ih  = (const float*)d_in[2];
    const float* b_ih  = (const float*)d_in[3];
    const float* W_hh  = (const float*)d_in[4];
    const float* b_hh  = (const float*)d_in[5];
    const float* W_c   = (const float*)d_in[6];
    const float* b_c   = (const float*)d_in[7];
    const float* W_d   = (const float*)d_in[8];
    const float* b_d   = (const float*)d_in[9];
    float* out = (float*)d_out;

    float *embproj, *zbuf, *Pbuf, *avbuf, *decbuf;
    cudaGetSymbolAddress((void**)&embproj, g_embproj);
    cudaGetSymbolAddress((void**)&zbuf,    g_z);
    cudaGetSymbolAddress((void**)&Pbuf,    g_P);
    cudaGetSymbolAddress((void**)&avbuf,   g_av);
    cudaGetSymbolAddress((void**)&decbuf,  g_dec);

    // 1. embproj[V,H] = emb @ W_ih^T + b_ih   (vocab-side projection)
    gemm_nt<<<dim3(4, 79, 1), 256>>>(emb, H_, 0, W_ih, H_, 0,
                                     embproj, H_, 0,
                                     V_, H_, H_, b_ih, 0);

    // 2. RNN scan -> z  (8 clusters of 8 CTAs)
    rnn_kernel<<<64, 512>>>(batch, embproj, W_hh, b_hh, zbuf);

    // 3. scores S = z @ z^T (causal tiles only) -> g_P
    gemm_nt<<<dim3(16, 16, B_), 256>>>(zbuf, H_, LH, zbuf, H_, LH,
                                       Pbuf, L_, LL,
                                       L_, L_, H_, nullptr, 2);

    // 4. row softmax in place
    softmax_rows<<<dim3(L_, B_), 256>>>(Pbuf);

    // 5. av = P @ z  (K limited per row tile)
    gemm_nn<<<dim3(4, 16, B_), 256>>>(Pbuf, L_, LL, zbuf, H_, LH,
                                      avbuf, H_, LH,
                                      L_, H_, L_, 1);

    // 6. fix row 0: uniform attention over all positions
    av0_mean<<<B_, 512>>>(zbuf, avbuf);

    // 7. dec = av @ W_c[:, :H]^T + b_c ; dec += z @ W_c[:, H:]^T
    gemm_nt<<<dim3(4, 128, 1), 256>>>(avbuf, H_, 0, W_c, 2 * H_, 0,
                                      decbuf, H_, 0,
                                      B_ * L_, H_, H_, b_c, 0);
    gemm_nt<<<dim3(4, 128, 1), 256>>>(zbuf, H_, 0, W_c + H_, 2 * H_, 0,
                                      decbuf, H_, 0,
                                      B_ * L_, H_, H_, nullptr, 1);

    // 8. logits = dec @ W_d^T + b_d
    gemm_nt<<<dim3(79, 128, 1), 256>>>(decbuf, H_, 0, W_d, H_, 0,
                                       out, V_, 0,
                                       B_ * L_, V_, H_, b_d, 0);
}